// round 11
// baseline (speedup 1.0000x reference)
#include <cuda_runtime.h>
#include <math.h>

#define BB 8
#define HH 512
#define WW 512
#define NPIX (BB*HH*WW)
#define TILE 16
#define HALO 2
#define SROWS (TILE + 2*HALO)     // 20 smem rows per block
#define NBLK ((HH/TILE)*BB)       // 256 blocks
#define DSENT 30000

// Per-block partials: [bid][0..4] = {intersect, sum p1^2, sum lab, ce, hd}
__device__ double g_blk[NBLK * 5];
__device__ unsigned g_count;   // zero-init at load; last block resets it

// Nearest-set-bit distance in a 512-bit row stored as 16 uint32 words
// (set bit == background). Returns linear distance, DSENT if none.
__device__ __forceinline__ int nz_d(const unsigned* z, int j) {
    int w  = j >> 5;
    int jb = j & 31;
    int dl = DSENT;
    unsigned t = z[w] & (0xFFFFFFFFu >> (31 - jb));
    if (t) {
        dl = jb - (31 - __clz(t));
    } else {
        #pragma unroll 4
        for (int ww = w - 1; ww >= 0; --ww) {
            unsigned zz = z[ww];
            if (zz) { dl = j - (ww * 32 + 31 - __clz(zz)); break; }
        }
    }
    int dr = DSENT;
    unsigned u = z[w] & (0xFFFFFFFFu << jb);
    if (u) {
        dr = (__ffs(u) - 1) - jb;
    } else {
        #pragma unroll 4
        for (int ww = w + 1; ww < 16; ++ww) {
            unsigned zz = z[ww];
            if (zz) { dr = ww * 32 + (__ffs(zz) - 1) - j; break; }
        }
    }
    return min(dl, dr);
}

// Pack per-thread 4-bit nibbles into 32-bit row-mask words.
__device__ __forceinline__ unsigned pack_nibbles(unsigned nib) {
    unsigned v = nib | (__shfl_xor_sync(0xFFFFFFFFu, nib, 1) << 4);
    v = v | (__shfl_xor_sync(0xFFFFFFFFu, v, 2) << 8);
    v = v | (__shfl_xor_sync(0xFFFFFFFFu, v, 4) << 16);
    return v;   // valid at lanes == 0 (mod 8)
}

// Exact slow-path: distance to nearest background pixel in row `row` around
// column j, for both masks, scanning gmem directly. Only reached when no
// background exists within the radius-2 window (prob ~2^-30 per pixel).
__device__ __noinline__ void rowdist2(const float* __restrict__ outputs,
                                      const int* __restrict__ label,
                                      int b, int row, int j, int& dg, int& ds) {
    size_t base = ((size_t)(b * 2 + 1) * HH + row) * WW;
    dg = DSENT; ds = DSENT;
    for (int d = 0; d < WW; d++) {
        int jl = j - d, jr = j + d;
        if (dg == DSENT) {
            bool hit = (jl >= 0 && label[base + jl] <= 0) ||
                       (jr < WW && label[base + jr] <= 0);
            if (hit) dg = d;
        }
        if (ds == DSENT) {
            bool hit = (jl >= 0 && outputs[base + jl] <= 0.5f) ||
                       (jr < WW && outputs[base + jr] <= 0.5f);
            if (hit) ds = d;
        }
        if (dg != DSENT && ds != DSENT) break;
    }
}

// Single fused kernel: row-EDT (with halo) into smem, column window from
// smem, CE/Dice/HD sums, last-block finalize. One launch, no global scratch
// except the tiny per-block partials.
__global__ void __launch_bounds__(512) fused_k(const float* __restrict__ outputs,
                                               const int* __restrict__ label,
                                               float* __restrict__ out) {
    int b   = blockIdx.y;
    int y0  = blockIdx.x * TILE;
    int t   = threadIdx.x;
    int grp = t >> 7;          // 0..3: row group within iteration
    int rt  = t & 127;         // thread within row
    int wg  = rt >> 5;         // warp within row group
    int lid = t & 31;
    int wid = t >> 5;
    int j4  = rt * 4;

    __shared__ unsigned short pack[SROWS][WW];   // 20 KB: u8 gt | u8 seg per px
    __shared__ unsigned zg[4][16], zs[4][16];
    __shared__ float sb[16][5];

    float v0 = 0.f, v1 = 0.f, v2 = 0.f, v3 = 0.f;

    // ── Row phase: 5 iterations × 4 rows (128 threads per row) ──
    for (int it = 0; it < SROWS / 4; it++) {
        int slot = it * 4 + grp;
        int rr   = min(max(y0 - HALO + slot, 0), HH - 1);   // clamped halo
        size_t base1 = ((size_t)(b * 2 + 1) * HH + rr) * WW;
        float4 p1v = *(const float4*)(outputs + base1 + j4);
        int4   lbv = *(const int4*)(label + base1 + j4);
        float p1a[4] = {p1v.x, p1v.y, p1v.z, p1v.w};
        int   lba[4] = {lbv.x, lbv.y, lbv.z, lbv.w};

        unsigned nibg = 0, nibs = 0;
        #pragma unroll
        for (int k = 0; k < 4; k++) {
            nibg |= (lba[k] > 0 ? 0u : 1u) << k;       // set bit == background
            nibs |= (p1a[k] > 0.5f ? 0u : 1u) << k;
        }
        unsigned wgm = pack_nibbles(nibg);
        unsigned wsm = pack_nibbles(nibs);
        if ((lid & 7) == 0) {
            int ws = wg * 4 + (lid >> 3);
            zg[grp][ws] = wgm;
            zs[grp][ws] = wsm;
        }
        __syncthreads();

        unsigned pk[4];
        #pragma unroll
        for (int k = 0; k < 4; k++) {
            int dg = min(nz_d(zg[grp], j4 + k), 255);
            int ds = min(nz_d(zs[grp], j4 + k), 255);
            pk[k] = (unsigned)dg | ((unsigned)ds << 8);
        }
        uint2 st;
        st.x = pk[0] | (pk[1] << 16);
        st.y = pk[2] | (pk[3] << 16);
        *(uint2*)&pack[slot][j4] = st;

        // CE/Dice only for interior (owned) rows; halo rows excluded.
        if (slot >= HALO && slot < HALO + TILE) {
            #pragma unroll
            for (int k = 0; k < 4; k++) {
                float p1 = p1a[k];
                float p0 = 1.0f - p1;                 // softmax rows sum to 1
                float labf = (lba[k] > 0) ? 1.0f : 0.0f;
                float mx   = fmaxf(p0, p1);
                float lse  = mx + __logf(__expf(p0 - mx) + __expf(p1 - mx));
                float picked = (lba[k] > 0) ? p1 : p0;
                v0 += p1 * labf;
                v1 += p1 * p1;
                v2 += labf;
                v3 += lse - picked;
            }
        }
        __syncthreads();   // zg/zs reuse next iteration; pack visible after loop
    }

    // ── Column phase: each thread does 4 px in 4 interior rows (16 px) ──
    float hd = 0.f;
    #pragma unroll
    for (int q = 0; q < 4; q++) {
        int slot = HALO + grp + q * 4;   // 2..17
        int i    = y0 + grp + q * 4;     // global row
        size_t base1 = ((size_t)(b * 2 + 1) * HH + i) * WW + j4;
        float4 p1v = *(const float4*)(outputs + base1);   // L2 hit
        uint2 c0 = *(const uint2*)&pack[slot][j4];
        uint2 u1 = *(const uint2*)&pack[slot - 1][j4];
        uint2 d1 = *(const uint2*)&pack[slot + 1][j4];
        uint2 u2 = *(const uint2*)&pack[slot - 2][j4];
        uint2 d2 = *(const uint2*)&pack[slot + 2][j4];

        unsigned c0w[2] = {c0.x, c0.y};
        unsigned m1w[2], m2w[2];
        m1w[0] = __vminu4(u1.x, d1.x); m1w[1] = __vminu4(u1.y, d1.y);
        m2w[0] = __vminu4(u2.x, d2.x); m2w[1] = __vminu4(u2.y, d2.y);

        float p1a[4] = {p1v.x, p1v.y, p1v.z, p1v.w};
        #pragma unroll
        for (int k = 0; k < 4; k++) {
            int sh = (k & 1) * 16;
            unsigned cw = c0w[k >> 1] >> sh;
            unsigned m1 = m1w[k >> 1] >> sh;
            unsigned m2 = m2w[k >> 1] >> sh;
            int dg = (int)(cw & 0xFFu), ds = (int)((cw >> 8) & 0xFFu);
            int g1 = (int)(m1 & 0xFFu), s1 = (int)((m1 >> 8) & 0xFFu);
            int g2 = (int)(m2 & 0xFFu), s2 = (int)((m2 >> 8) & 0xFFu);
            int g = min(dg * dg, min(g1 * g1 + 1, g2 * g2 + 4));
            int s = min(ds * ds, min(s1 * s1 + 1, s2 * s2 + 4));

            if (g > 9 || s > 9) {   // exact rare tail via direct gmem scans
                int j = j4 + k;
                for (int r = 3; r < HH; r++) {
                    int r2 = r * r;
                    if (r2 >= g && r2 >= s) break;
                    if (i - r >= 0) {
                        int a, c; rowdist2(outputs, label, b, i - r, j, a, c);
                        g = min(g, a * a + r2); s = min(s, c * c + r2);
                    }
                    if (i + r < HH) {
                        int a, c; rowdist2(outputs, label, b, i + r, j, a, c);
                        g = min(g, a * a + r2); s = min(s, c * c + r2);
                    }
                }
            }

            float labf = (dg != 0) ? 1.0f : 0.0f;   // dg>0 <=> lab>0
            float dlt  = p1a[k] - labf;
            hd += (dlt * dlt) * ((float)g + (float)s);
        }
    }

    // ── Block reduction (fp32 warp, fp64 block) ──
    #pragma unroll
    for (int off = 16; off > 0; off >>= 1) {
        v0 += __shfl_down_sync(0xFFFFFFFFu, v0, off);
        v1 += __shfl_down_sync(0xFFFFFFFFu, v1, off);
        v2 += __shfl_down_sync(0xFFFFFFFFu, v2, off);
        v3 += __shfl_down_sync(0xFFFFFFFFu, v3, off);
        hd += __shfl_down_sync(0xFFFFFFFFu, hd, off);
    }
    if (lid == 0) {
        sb[wid][0] = v0; sb[wid][1] = v1; sb[wid][2] = v2;
        sb[wid][3] = v3; sb[wid][4] = hd;
    }
    __syncthreads();

    int bid = blockIdx.y * gridDim.x + blockIdx.x;
    if (t == 0) {
        double d0=0, d1=0, d2=0, d3=0, dh=0;
        #pragma unroll
        for (int w = 0; w < 16; w++) {
            d0 += (double)sb[w][0]; d1 += (double)sb[w][1];
            d2 += (double)sb[w][2]; d3 += (double)sb[w][3];
            dh += (double)sb[w][4];
        }
        g_blk[bid * 5 + 0] = d0;
        g_blk[bid * 5 + 1] = d1;
        g_blk[bid * 5 + 2] = d2;
        g_blk[bid * 5 + 3] = d3;
        g_blk[bid * 5 + 4] = dh;
    }

    // ── last-block finalize ──
    __shared__ bool isLast;
    if (t == 0) {
        __threadfence();
        unsigned c = atomicAdd(&g_count, 1u);
        isLast = (c == NBLK - 1);
    }
    __syncthreads();
    if (!isLast) return;
    __threadfence();

    double s0 = 0.0, s1 = 0.0, s2 = 0.0, s3 = 0.0, sh = 0.0;
    for (int k = t; k < NBLK; k += 512) {
        s0 += g_blk[k * 5 + 0];
        s1 += g_blk[k * 5 + 1];
        s2 += g_blk[k * 5 + 2];
        s3 += g_blk[k * 5 + 3];
        sh += g_blk[k * 5 + 4];
    }
    #pragma unroll
    for (int off = 16; off > 0; off >>= 1) {
        s0 += __shfl_down_sync(0xFFFFFFFFu, s0, off);
        s1 += __shfl_down_sync(0xFFFFFFFFu, s1, off);
        s2 += __shfl_down_sync(0xFFFFFFFFu, s2, off);
        s3 += __shfl_down_sync(0xFFFFFFFFu, s3, off);
        sh += __shfl_down_sync(0xFFFFFFFFu, sh, off);
    }
    __shared__ double fb[16][5];
    if (lid == 0) { fb[wid][0]=s0; fb[wid][1]=s1; fb[wid][2]=s2; fb[wid][3]=s3; fb[wid][4]=sh; }
    __syncthreads();
    if (t == 0) {
        double a0=0, a1=0, a2=0, a3=0, ah=0;
        #pragma unroll
        for (int w = 0; w < 16; w++) {
            a0 += fb[w][0]; a1 += fb[w][1]; a2 += fb[w][2]; a3 += fb[w][3]; ah += fb[w][4];
        }
        double N    = (double)NPIX;
        double hdm  = ah / N;
        double dice = 1.0 - (2.0 * a0 + 1e-6) / (a1 + a2 + 1e-6);
        double ce   = a3 / N;
        // LAM = 1.0, ALPHA = 0.5 -> loss = (ce + dice) + 0.5 * hd
        out[0] = (float)((ce + dice) + 0.5 * hdm);
        g_count = 0;   // reset for next graph replay
    }
}

extern "C" void kernel_launch(void* const* d_in, const int* in_sizes, int n_in,
                              void* d_out, int out_size) {
    const float* outputs = (const float*)d_in[0];
    const int*   label   = (const int*)d_in[1];
    float*       out     = (float*)d_out;

    dim3 grid(HH / TILE, BB);
    fused_k<<<grid, 512>>>(outputs, label, out);
}

// round 12
// speedup vs baseline: 1.1034x; 1.1034x over previous
#include <cuda_runtime.h>
#include <math.h>

#define BB 8
#define HH 512
#define WW 512
#define NPIX (BB*HH*WW)

#define NBLK1 (BB*HH)         // 4096 pass1 blocks (one per row)
#define NBLK2 (2*64*8)        // 1024 pass2 blocks (256 cols x 8 rows, 8 px/thread)
#define DSENT 30000

// Packed row-EDT distances, u8 per mask saturated at 255:
// byte0 = gt distance, byte1 = seg distance (2 bytes per pixel).
__device__ unsigned short g_pack[NPIX];
// Per-block partial sums (no hot atomics).
__device__ double g_part[NBLK1 * 4];
__device__ double g_hd[NBLK2];
__device__ unsigned g_count;   // zero-init at load; last block resets it

// Nearest-set-bit distance in a 512-bit row stored as 16 uint32 words
// (set bit == background). Returns linear distance, DSENT if none.
__device__ __forceinline__ int nz_d(const unsigned* __restrict__ z, int j) {
    int w  = j >> 5;
    int jb = j & 31;
    int dl = DSENT;
    unsigned t = z[w] & (0xFFFFFFFFu >> (31 - jb));
    if (t) {
        dl = jb - (31 - __clz(t));
    } else {
        #pragma unroll 4
        for (int ww = w - 1; ww >= 0; --ww) {
            unsigned zz = z[ww];
            if (zz) { dl = j - (ww * 32 + 31 - __clz(zz)); break; }
        }
    }
    int dr = DSENT;
    unsigned u = z[w] & (0xFFFFFFFFu << jb);
    if (u) {
        dr = (__ffs(u) - 1) - jb;
    } else {
        #pragma unroll 4
        for (int ww = w + 1; ww < 16; ++ww) {
            unsigned zz = z[ww];
            if (zz) { dr = ww * 32 + (__ffs(zz) - 1) - j; break; }
        }
    }
    return min(dl, dr);
}

// Pack per-thread 4-bit nibbles into 32-bit row-mask words.
__device__ __forceinline__ unsigned pack_nibbles(unsigned nib) {
    unsigned v = nib | (__shfl_xor_sync(0xFFFFFFFFu, nib, 1) << 4);
    v = v | (__shfl_xor_sync(0xFFFFFFFFu, v, 2) << 8);
    v = v | (__shfl_xor_sync(0xFFFFFFFFu, v, 4) << 16);
    return v;   // valid at lanes == 0 (mod 8)
}

// Cold exact tail: column search beyond radius 2 reading packed rows from
// gmem. Essentially never executed (P ~ 2^-25 per pixel); __noinline__ keeps
// its registers out of the hot path.
__device__ __noinline__ void tail_scan(const unsigned short* __restrict__ Pb,
                                       int i, int j, int& g, int& s) {
    for (int r = 3; r < HH; r++) {
        int r2 = r * r;
        if (r2 >= g && r2 >= s) break;
        if (i - r >= 0) {
            unsigned cc = Pb[(size_t)(i - r) * WW + j];
            int vg = (int)(cc & 0xFFu);
            int vs = (int)(cc >> 8);
            g = min(g, vg * vg + r2);
            s = min(s, vs * vs + r2);
        }
        if (i + r < HH) {
            unsigned cc = Pb[(size_t)(i + r) * WW + j];
            int vg = (int)(cc & 0xFFu);
            int vs = (int)(cc >> 8);
            g = min(g, vg * vg + r2);
            s = min(s, vs * vs + r2);
        }
    }
}

// Pass 1: 128 threads per (batch,row), 4 pixels each (round-10 known-good).
__global__ void __launch_bounds__(128) pass1_k(const float* __restrict__ outputs,
                                               const int* __restrict__ label) {
    int row = blockIdx.x;
    int b   = blockIdx.y;
    int t   = threadIdx.x;
    int wid = t >> 5, lid = t & 31;
    int j4  = t * 4;

    __shared__ unsigned zg[16];   // set bit == (lab == 0)
    __shared__ unsigned zs[16];   // set bit == (p1 <= 0.5)

    size_t base1 = ((size_t)(b * 2 + 1) * HH + row) * WW;
    float4 p1v = *(const float4*)(outputs + base1 + j4);
    int4   lbv = *(const int4*)(label + base1 + j4);

    float p1a[4] = {p1v.x, p1v.y, p1v.z, p1v.w};
    int   lba[4] = {lbv.x, lbv.y, lbv.z, lbv.w};

    unsigned nibg = 0, nibs = 0;
    #pragma unroll
    for (int k = 0; k < 4; k++) {
        nibg |= (lba[k] > 0 ? 0u : 1u) << k;       // set bit == background
        nibs |= (p1a[k] > 0.5f ? 0u : 1u) << k;
    }
    unsigned wg = pack_nibbles(nibg);
    unsigned ws = pack_nibbles(nibs);
    if ((lid & 7) == 0) {
        int wslot = wid * 4 + (lid >> 3);
        zg[wslot] = wg;
        zs[wslot] = ws;
    }
    __syncthreads();

    unsigned pk[4];
    #pragma unroll
    for (int k = 0; k < 4; k++) {
        int dg = min(nz_d(zg, j4 + k), 255);
        int ds = min(nz_d(zs, j4 + k), 255);
        pk[k] = (unsigned)dg | ((unsigned)ds << 8);
    }
    uint2 st;
    st.x = pk[0] | (pk[1] << 16);
    st.y = pk[2] | (pk[3] << 16);
    *(uint2*)(g_pack + ((size_t)b * HH + row) * WW + j4) = st;

    // Pointwise CE/Dice terms (fast-math; p0 = 1 - p1)
    float v0 = 0.f, v1 = 0.f, v2 = 0.f, v3 = 0.f;
    #pragma unroll
    for (int k = 0; k < 4; k++) {
        float p1 = p1a[k];
        float p0 = 1.0f - p1;
        float labf = (lba[k] > 0) ? 1.0f : 0.0f;
        float mx   = fmaxf(p0, p1);
        float lse  = mx + __logf(__expf(p0 - mx) + __expf(p1 - mx));
        float picked = (lba[k] > 0) ? p1 : p0;
        v0 += p1 * labf;
        v1 += p1 * p1;
        v2 += labf;
        v3 += lse - picked;
    }

    #pragma unroll
    for (int off = 16; off > 0; off >>= 1) {
        v0 += __shfl_down_sync(0xFFFFFFFFu, v0, off);
        v1 += __shfl_down_sync(0xFFFFFFFFu, v1, off);
        v2 += __shfl_down_sync(0xFFFFFFFFu, v2, off);
        v3 += __shfl_down_sync(0xFFFFFFFFu, v3, off);
    }
    __shared__ float sb[4][4];
    if (lid == 0) { sb[wid][0] = v0; sb[wid][1] = v1; sb[wid][2] = v2; sb[wid][3] = v3; }
    __syncthreads();
    if (t < 4) {
        double s = 0.0;
        #pragma unroll
        for (int w = 0; w < 4; w++) s += (double)sb[w][t];
        g_part[(b * HH + row) * 4 + t] = s;
    }
}

// Pass 2: column EDT, 8 px/thread via u8-packed uint4 window loads.
// min-6-blocks launch bound raises occupancy to ~75%; cold tail extracted.
__global__ void __launch_bounds__(256, 6) pass2_k(const float* __restrict__ outputs,
                                                  float* __restrict__ out) {
    int b  = blockIdx.z;
    int i  = blockIdx.y * 8 + threadIdx.y;               // row
    int j8 = (blockIdx.x * 32 + threadIdx.x) * 8;        // first of 8 columns

    const unsigned short* __restrict__ Pb = g_pack + (size_t)b * HH * WW;

    // p1 issued early to overlap with window loads
    size_t base1 = ((size_t)(b * 2 + 1) * HH + i) * WW + j8;
    float4 p1lo = *(const float4*)(outputs + base1);
    float4 p1hi = *(const float4*)(outputs + base1 + 4);

    int iu1 = max(i - 1, 0), id1 = min(i + 1, HH - 1);
    int iu2 = max(i - 2, 0), id2 = min(i + 2, HH - 1);

    uint4 c0v = *(const uint4*)(Pb + (size_t)i   * WW + j8);
    uint4 u1v = *(const uint4*)(Pb + (size_t)iu1 * WW + j8);
    uint4 d1v = *(const uint4*)(Pb + (size_t)id1 * WW + j8);
    uint4 u2v = *(const uint4*)(Pb + (size_t)iu2 * WW + j8);
    uint4 d2v = *(const uint4*)(Pb + (size_t)id2 * WW + j8);

    const unsigned* c0w = (const unsigned*)&c0v;
    const unsigned* u1w = (const unsigned*)&u1v;
    const unsigned* d1w = (const unsigned*)&d1v;
    const unsigned* u2w = (const unsigned*)&u2v;
    const unsigned* d2w = (const unsigned*)&d2v;

    float p1a[8] = {p1lo.x, p1lo.y, p1lo.z, p1lo.w, p1hi.x, p1hi.y, p1hi.z, p1hi.w};
    float hd = 0.f;

    #pragma unroll
    for (int k = 0; k < 4; k++) {
        unsigned m1 = __vminu4(u1w[k], d1w[k]);   // per-byte min, radius 1
        unsigned m2 = __vminu4(u2w[k], d2w[k]);   // per-byte min, radius 2
        #pragma unroll
        for (int h = 0; h < 2; h++) {
            int px = 2 * k + h;
            unsigned cw = c0w[k] >> (h * 16);
            unsigned w1 = m1 >> (h * 16);
            unsigned w2 = m2 >> (h * 16);
            int dg = (int)(cw & 0xFFu), ds = (int)((cw >> 8) & 0xFFu);
            int g1 = (int)(w1 & 0xFFu), s1 = (int)((w1 >> 8) & 0xFFu);
            int g2 = (int)(w2 & 0xFFu), s2 = (int)((w2 >> 8) & 0xFFu);
            int g = min(dg * dg, min(g1 * g1 + 1, g2 * g2 + 4));
            int s = min(ds * ds, min(s1 * s1 + 1, s2 * s2 + 4));
            if (g > 9 || s > 9)
                tail_scan(Pb, i, j8 + px, g, s);
            float labf = (dg != 0) ? 1.0f : 0.0f;   // dg>0 <=> lab>0
            float dlt  = p1a[px] - labf;
            hd += (dlt * dlt) * ((float)g + (float)s);
        }
    }

    #pragma unroll
    for (int off = 16; off > 0; off >>= 1)
        hd += __shfl_down_sync(0xFFFFFFFFu, hd, off);

    __shared__ double sbh[8];
    int tid = threadIdx.y * 32 + threadIdx.x;
    int wid = tid >> 5, lid = tid & 31;
    if (lid == 0) sbh[wid] = (double)hd;
    __syncthreads();

    int bid = (blockIdx.z * gridDim.y + blockIdx.y) * gridDim.x + blockIdx.x;
    if (tid < 8) {
        double s = sbh[tid];
        #pragma unroll
        for (int off = 4; off > 0; off >>= 1)
            s += __shfl_down_sync(0x000000FFu, s, off);
        if (tid == 0) g_hd[bid] = s;
    }

    // ── last-block finalize ──
    __shared__ bool isLast;
    if (tid == 0) {
        __threadfence();
        unsigned cnum = atomicAdd(&g_count, 1u);
        isLast = (cnum == NBLK2 - 1);
    }
    __syncthreads();
    if (!isLast) return;
    __threadfence();

    double s0 = 0.0, s1 = 0.0, s2 = 0.0, s3 = 0.0, sh = 0.0;
    for (int k = tid; k < NBLK1; k += 256) {
        s0 += g_part[k * 4 + 0];
        s1 += g_part[k * 4 + 1];
        s2 += g_part[k * 4 + 2];
        s3 += g_part[k * 4 + 3];
    }
    for (int k = tid; k < NBLK2; k += 256) sh += g_hd[k];

    #pragma unroll
    for (int off = 16; off > 0; off >>= 1) {
        s0 += __shfl_down_sync(0xFFFFFFFFu, s0, off);
        s1 += __shfl_down_sync(0xFFFFFFFFu, s1, off);
        s2 += __shfl_down_sync(0xFFFFFFFFu, s2, off);
        s3 += __shfl_down_sync(0xFFFFFFFFu, s3, off);
        sh += __shfl_down_sync(0xFFFFFFFFu, sh, off);
    }
    __shared__ double fb[8][5];
    if (lid == 0) { fb[wid][0]=s0; fb[wid][1]=s1; fb[wid][2]=s2; fb[wid][3]=s3; fb[wid][4]=sh; }
    __syncthreads();
    if (tid == 0) {
        double a0d=0, a1d=0, a2d=0, a3d=0, ahd=0;
        #pragma unroll
        for (int w = 0; w < 8; w++) {
            a0d += fb[w][0]; a1d += fb[w][1]; a2d += fb[w][2]; a3d += fb[w][3]; ahd += fb[w][4];
        }
        double N    = (double)NPIX;
        double hdm  = ahd / N;
        double dice = 1.0 - (2.0 * a0d + 1e-6) / (a1d + a2d + 1e-6);
        double ce   = a3d / N;
        // LAM = 1.0, ALPHA = 0.5 -> loss = (ce + dice) + 0.5 * hd
        out[0] = (float)((ce + dice) + 0.5 * hdm);
        g_count = 0;   // reset for next graph replay
    }
}

extern "C" void kernel_launch(void* const* d_in, const int* in_sizes, int n_in,
                              void* d_out, int out_size) {
    const float* outputs = (const float*)d_in[0];
    const int*   label   = (const int*)d_in[1];
    float*       out     = (float*)d_out;

    dim3 g1(HH, BB);
    pass1_k<<<g1, 128>>>(outputs, label);

    dim3 b2(32, 8);   // 256 threads: 32 col-threads (8 px each) x 8 rows
    dim3 g2(2, 64, BB);
    pass2_k<<<g2, b2>>>(outputs, out);
}